// round 3
// baseline (speedup 1.0000x reference)
#include <cuda_runtime.h>

// Problem constants
#define NTOK   65536        // B*D*H*W tokens
#define NC     64           // channels
#define KCB    4096         // codebook size
#define SPAT   32768        // D*H*W
#define OUT_ELEMS 4194304   // 2*64*8*64*64
#define LOSS_OFF  OUT_ELEMS
#define IDX_OFF   (OUT_ELEMS + 2)

// Scratch (allocation-free rule: __device__ globals)
__device__ float g_t[NTOK * NC];    // pre-conv tokens, row-major (n, c)
__device__ float g_eh[KCB];         // 0.5 * |e_k|^2
__device__ int   g_idx[NTOK];
__device__ float g_loss;

// Packed fp32x2 FMA (sm_100+): d.lo += a.lo*b.lo ; d.hi += a.hi*b.hi
__device__ __forceinline__ void fma2(unsigned long long& d,
                                     unsigned long long a,
                                     unsigned long long b) {
    asm("fma.rn.f32x2 %0, %1, %2, %0;" : "+l"(d) : "l"(a), "l"(b));
}
__device__ __forceinline__ float pair_sum(unsigned long long v) {
    float lo = __uint_as_float((unsigned)(v & 0xffffffffu));
    float hi = __uint_as_float((unsigned)(v >> 32));
    return lo + hi;
}

// ---------------------------------------------------------------------------
__global__ void k_eh(const float* __restrict__ E) {
    int k = blockIdx.x * 256 + threadIdx.x;
    if (k == 0) g_loss = 0.0f;
    const float4* row = (const float4*)(E + k * NC);
    float s = 0.0f;
#pragma unroll
    for (int i = 0; i < 16; i++) {
        float4 v = row[i];
        s += v.x * v.x + v.y * v.y + v.z * v.z + v.w * v.w;
    }
    g_eh[k] = 0.5f * s;
}

// ---------------------------------------------------------------------------
// pre-conv: t[n][o] = pre_b[o] + sum_c pre_w[o][c] * z[b][c][s]
__global__ void __launch_bounds__(256) k_preconv(const float* __restrict__ z,
                                                 const float* __restrict__ w,
                                                 const float* __restrict__ b) {
    __shared__ float shW[NC * NC];
    __shared__ float shB[NC];
    int tid = threadIdx.x;
    for (int i = tid; i < NC * NC; i += 256) shW[i] = w[i];
    if (tid < NC) shB[tid] = b[tid];
    __syncthreads();

    int n  = blockIdx.x * 256 + tid;
    int bb = n >> 15;
    int s  = n & 32767;
    const float* zp = z + bb * (NC * SPAT) + s;

    float zin[NC];
#pragma unroll
    for (int c = 0; c < NC; c++) zin[c] = zp[c * SPAT];

    float* trow = g_t + n * NC;
#pragma unroll 1
    for (int og = 0; og < 16; og++) {
        float a0 = shB[og * 4 + 0], a1 = shB[og * 4 + 1];
        float a2 = shB[og * 4 + 2], a3 = shB[og * 4 + 3];
#pragma unroll
        for (int c = 0; c < NC; c += 4) {
            float4 w0 = *(const float4*)&shW[(og * 4 + 0) * NC + c];
            float4 w1 = *(const float4*)&shW[(og * 4 + 1) * NC + c];
            float4 w2 = *(const float4*)&shW[(og * 4 + 2) * NC + c];
            float4 w3 = *(const float4*)&shW[(og * 4 + 3) * NC + c];
            a0 += w0.x * zin[c] + w0.y * zin[c + 1] + w0.z * zin[c + 2] + w0.w * zin[c + 3];
            a1 += w1.x * zin[c] + w1.y * zin[c + 1] + w1.z * zin[c + 2] + w1.w * zin[c + 3];
            a2 += w2.x * zin[c] + w2.y * zin[c + 1] + w2.z * zin[c + 2] + w2.w * zin[c + 3];
            a3 += w3.x * zin[c] + w3.y * zin[c + 1] + w3.z * zin[c + 2] + w3.w * zin[c + 3];
        }
        float4 o4 = make_float4(a0, a1, a2, a3);
        *(float4*)(trow + og * 4) = o4;
    }
}

// ---------------------------------------------------------------------------
// Fused distance + argmin.  Block tile: 64 tokens x 64 codes/chunk, 64 chunks.
// Thread microtile: 4 tokens x 4 codes.  Code assignment per thread is
// {tx*2, tx*2+1, tx*2+32, tx*2+33} so the two LDS.128 E-loads are bank-dense
// (16 lanes x 16B contiguous = all 32 banks once; no conflicts).
__global__ void __launch_bounds__(256) k_argmin(const float* __restrict__ E) {
    __shared__ float2 shT[32][64];   // [c-pair][token]
    __shared__ float2 shE[32][64];   // [c-pair][code]
    __shared__ float  shEh[64];

    int tid = threadIdx.x;
    int tx = tid & 15;   // code group
    int ty = tid >> 4;   // token group
    int tok0 = blockIdx.x * 64;

    // load token tile (transposed pairs)
    for (int i = tid; i < 2048; i += 256) {
        int m = i >> 5, cp = i & 31;
        shT[cp][m] = *(const float2*)(g_t + (tok0 + m) * NC + 2 * cp);
    }

    float bestD[4] = {1e30f, 1e30f, 1e30f, 1e30f};
    int   bestI[4] = {0, 0, 0, 0};

    for (int kc = 0; kc < 64; kc++) {
        int k0 = kc * 64;
        __syncthreads();
        for (int i = tid; i < 2048; i += 256) {
            int cd = i >> 5, cp = i & 31;
            shE[cp][cd] = *(const float2*)(E + (k0 + cd) * NC + 2 * cp);
        }
        if (tid < 64) shEh[tid] = g_eh[k0 + tid];
        __syncthreads();

        unsigned long long acc[4][4];
#pragma unroll
        for (int i = 0; i < 4; i++)
#pragma unroll
            for (int j = 0; j < 4; j++) acc[i][j] = 0ull;

#pragma unroll
        for (int cp = 0; cp < 32; cp++) {
            ulonglong2 tA = *(const ulonglong2*)&shT[cp][ty * 4];
            ulonglong2 tB = *(const ulonglong2*)&shT[cp][ty * 4 + 2];
            // codes tx*2, tx*2+1 (eA) and tx*2+32, tx*2+33 (eB): bank-dense
            ulonglong2 eA = *(const ulonglong2*)&shE[cp][tx * 2];
            ulonglong2 eB = *(const ulonglong2*)&shE[cp][tx * 2 + 32];
            fma2(acc[0][0], tA.x, eA.x); fma2(acc[0][1], tA.x, eA.y);
            fma2(acc[0][2], tA.x, eB.x); fma2(acc[0][3], tA.x, eB.y);
            fma2(acc[1][0], tA.y, eA.x); fma2(acc[1][1], tA.y, eA.y);
            fma2(acc[1][2], tA.y, eB.x); fma2(acc[1][3], tA.y, eB.y);
            fma2(acc[2][0], tB.x, eA.x); fma2(acc[2][1], tB.x, eA.y);
            fma2(acc[2][2], tB.x, eB.x); fma2(acc[2][3], tB.x, eB.y);
            fma2(acc[3][0], tB.y, eA.x); fma2(acc[3][1], tB.y, eA.y);
            fma2(acc[3][2], tB.y, eB.x); fma2(acc[3][3], tB.y, eB.y);
        }

        // code index for (j): j=0 -> tx*2, j=1 -> tx*2+1, j=2 -> tx*2+32, j=3 -> tx*2+33
#pragma unroll
        for (int i = 0; i < 4; i++) {
#pragma unroll
            for (int j = 0; j < 4; j++) {
                int ck = tx * 2 + (j & 1) + ((j >> 1) << 5);
                float d = shEh[ck] - pair_sum(acc[i][j]);
                if (d < bestD[i]) { bestD[i] = d; bestI[i] = k0 + ck; }
            }
        }
    }

    // cross-thread reduction (16 code-groups per token).
    // NOTE: min over all 16 groups x 4 j-slots covers every code exactly once,
    // but per-(i) slots now hold interleaved code sets; tie-break by lowest
    // index still requires comparing indices, which we do.
    __syncthreads();
    float* red_val = (float*)&shE[0][0];          // 64*16 floats
    int*   red_idx = (int*)(red_val + 64 * 16);   // 64*16 ints
#pragma unroll
    for (int i = 0; i < 4; i++) {
        red_val[(ty * 4 + i) * 16 + tx] = bestD[i];
        red_idx[(ty * 4 + i) * 16 + tx] = bestI[i];
    }
    __syncthreads();
    if (tid < 64) {
        float bv = red_val[tid * 16];
        int   bi = red_idx[tid * 16];
        for (int x = 1; x < 16; x++) {
            float v  = red_val[tid * 16 + x];
            int   id = red_idx[tid * 16 + x];
            if (v < bv || (v == bv && id < bi)) { bv = v; bi = id; }
        }
        g_idx[tok0 + tid] = bi;
    }
}

// ---------------------------------------------------------------------------
// gather codebook row, post-conv, loss accumulation, index output
__global__ void __launch_bounds__(256) k_post(const float* __restrict__ E,
                                              const float* __restrict__ w,
                                              const float* __restrict__ b,
                                              float* __restrict__ out) {
    __shared__ float shW[NC * NC];
    __shared__ float shB[NC];
    __shared__ float red[256];
    int tid = threadIdx.x;
    for (int i = tid; i < NC * NC; i += 256) shW[i] = w[i];
    if (tid < NC) shB[tid] = b[tid];
    __syncthreads();

    int n   = blockIdx.x * 256 + tid;
    int idx = g_idx[n];
    const float4* erow = (const float4*)(E + idx * NC);
    const float4* trow = (const float4*)(g_t + n * NC);

    float ein[NC];
    float loss = 0.0f;
#pragma unroll
    for (int i = 0; i < 16; i++) {
        float4 e4 = erow[i];
        float4 t4 = trow[i];
        ein[4 * i + 0] = e4.x; ein[4 * i + 1] = e4.y;
        ein[4 * i + 2] = e4.z; ein[4 * i + 3] = e4.w;
        float dx = e4.x - t4.x, dy = e4.y - t4.y;
        float dz = e4.z - t4.z, dw = e4.w - t4.w;
        loss += dx * dx + dy * dy + dz * dz + dw * dw;
    }

    int bb = n >> 15;
    int s  = n & 32767;
    float* op = out + bb * (NC * SPAT) + s;
#pragma unroll 1
    for (int og = 0; og < 16; og++) {
        float a0 = shB[og * 4 + 0], a1 = shB[og * 4 + 1];
        float a2 = shB[og * 4 + 2], a3 = shB[og * 4 + 3];
#pragma unroll
        for (int c = 0; c < NC; c += 4) {
            float4 w0 = *(const float4*)&shW[(og * 4 + 0) * NC + c];
            float4 w1 = *(const float4*)&shW[(og * 4 + 1) * NC + c];
            float4 w2 = *(const float4*)&shW[(og * 4 + 2) * NC + c];
            float4 w3 = *(const float4*)&shW[(og * 4 + 3) * NC + c];
            a0 += w0.x * ein[c] + w0.y * ein[c + 1] + w0.z * ein[c + 2] + w0.w * ein[c + 3];
            a1 += w1.x * ein[c] + w1.y * ein[c + 1] + w1.z * ein[c + 2] + w1.w * ein[c + 3];
            a2 += w2.x * ein[c] + w2.y * ein[c + 1] + w2.z * ein[c + 2] + w2.w * ein[c + 3];
            a3 += w3.x * ein[c] + w3.y * ein[c + 1] + w3.z * ein[c + 2] + w3.w * ein[c + 3];
        }
        op[(og * 4 + 0) * SPAT] = a0;
        op[(og * 4 + 1) * SPAT] = a1;
        op[(og * 4 + 2) * SPAT] = a2;
        op[(og * 4 + 3) * SPAT] = a3;
    }

    out[IDX_OFF + n] = (float)idx;

    // block loss reduction
    red[tid] = loss;
    __syncthreads();
    for (int off = 128; off > 0; off >>= 1) {
        if (tid < off) red[tid] += red[tid + off];
        __syncthreads();
    }
    if (tid == 0) atomicAdd(&g_loss, red[0]);
}

__global__ void k_fin(float* __restrict__ out) {
    float v = g_loss * (1.0f / ((float)NTOK * (float)NC));
    out[LOSS_OFF]     = v;  // codebook_loss
    out[LOSS_OFF + 1] = v;  // commitment_loss (same forward value)
}

// ---------------------------------------------------------------------------
extern "C" void kernel_launch(void* const* d_in, const int* in_sizes, int n_in,
                              void* d_out, int out_size) {
    const float* z      = (const float*)d_in[0];
    const float* emb    = (const float*)d_in[1];
    const float* pre_w  = (const float*)d_in[2];
    const float* pre_b  = (const float*)d_in[3];
    const float* post_w = (const float*)d_in[4];
    const float* post_b = (const float*)d_in[5];
    float* out = (float*)d_out;

    k_eh<<<KCB / 256, 256>>>(emb);
    k_preconv<<<NTOK / 256, 256>>>(z, pre_w, pre_b);
    k_argmin<<<NTOK / 64, 256>>>(emb);
    k_post<<<NTOK / 256, 256>>>(emb, post_w, post_b, out);
    k_fin<<<1, 1>>>(out);
}

// round 8
// speedup vs baseline: 1.7886x; 1.7886x over previous
#include <cuda_runtime.h>
#include <cstdint>

// Problem constants
#define NTOK   65536        // B*D*H*W tokens
#define NC     64           // channels
#define KCB    4096         // codebook size
#define SPAT   32768        // D*H*W
#define OUT_ELEMS 4194304   // 2*64*8*64*64
#define LOSS_OFF  OUT_ELEMS
#define IDX_OFF   (OUT_ELEMS + 2)

// Scratch (allocation-free rule: __device__ globals)
__device__ float g_t  [NTOK * NC];      // pre-conv tokens fp32 (for loss/post path)
__device__ float g_thi[NTOK * NC];      // tf32-hi split of tokens
__device__ float g_tlo[NTOK * NC];      // residual lo
__device__ float g_ehl[KCB * NC * 2];   // codebook split, interleaved (hi,lo) per (code,c)
__device__ float g_eh [KCB];            // 0.5*|e_k|^2
__device__ int   g_idx[NTOK];
__device__ float g_loss;

__device__ __forceinline__ float tf32_rna(float x) {
    uint32_t r;
    asm("cvt.rna.tf32.f32 %0, %1;" : "=r"(r) : "f"(x));
    return __uint_as_float(r);
}

// m16n8k8 tf32 MMA, D += A*B (accumulate in place)
__device__ __forceinline__ void mma_tf32(float& c0, float& c1, float& c2, float& c3,
                                         uint32_t a0, uint32_t a1, uint32_t a2, uint32_t a3,
                                         uint32_t b0, uint32_t b1) {
    asm("mma.sync.aligned.m16n8k8.row.col.f32.tf32.tf32.f32 "
        "{%0,%1,%2,%3}, {%4,%5,%6,%7}, {%8,%9}, {%0,%1,%2,%3};"
        : "+f"(c0), "+f"(c1), "+f"(c2), "+f"(c3)
        : "r"(a0), "r"(a1), "r"(a2), "r"(a3), "r"(b0), "r"(b1));
}

// ---------------------------------------------------------------------------
// codebook prep: eh = 0.5*|e|^2, plus tf32 hi/lo split (interleaved)
__global__ void k_eh(const float* __restrict__ E) {
    int k = blockIdx.x * 256 + threadIdx.x;
    if (k == 0) g_loss = 0.0f;
    const float* row = E + k * NC;
    float2* dst = (float2*)(g_ehl) + k * NC;
    float s = 0.0f;
#pragma unroll
    for (int c = 0; c < NC; c++) {
        float v = row[c];
        s += v * v;
        float hi = tf32_rna(v);
        dst[c] = make_float2(hi, v - hi);
    }
    g_eh[k] = 0.5f * s;
}

// ---------------------------------------------------------------------------
// pre-conv: t[n][o] = pre_b[o] + sum_c pre_w[o][c] * z[b][c][s]; also hi/lo split
__global__ void __launch_bounds__(256) k_preconv(const float* __restrict__ z,
                                                 const float* __restrict__ w,
                                                 const float* __restrict__ b) {
    __shared__ float shW[NC * NC];
    __shared__ float shB[NC];
    int tid = threadIdx.x;
    for (int i = tid; i < NC * NC; i += 256) shW[i] = w[i];
    if (tid < NC) shB[tid] = b[tid];
    __syncthreads();

    int n  = blockIdx.x * 256 + tid;
    int bb = n >> 15;
    int s  = n & 32767;
    const float* zp = z + bb * (NC * SPAT) + s;

    float zin[NC];
#pragma unroll
    for (int c = 0; c < NC; c++) zin[c] = zp[c * SPAT];

    float* trow  = g_t   + n * NC;
    float* hrow  = g_thi + n * NC;
    float* lrow  = g_tlo + n * NC;
#pragma unroll 1
    for (int og = 0; og < 16; og++) {
        float a0 = shB[og * 4 + 0], a1 = shB[og * 4 + 1];
        float a2 = shB[og * 4 + 2], a3 = shB[og * 4 + 3];
#pragma unroll
        for (int c = 0; c < NC; c += 4) {
            float4 w0 = *(const float4*)&shW[(og * 4 + 0) * NC + c];
            float4 w1 = *(const float4*)&shW[(og * 4 + 1) * NC + c];
            float4 w2 = *(const float4*)&shW[(og * 4 + 2) * NC + c];
            float4 w3 = *(const float4*)&shW[(og * 4 + 3) * NC + c];
            a0 += w0.x * zin[c] + w0.y * zin[c + 1] + w0.z * zin[c + 2] + w0.w * zin[c + 3];
            a1 += w1.x * zin[c] + w1.y * zin[c + 1] + w1.z * zin[c + 2] + w1.w * zin[c + 3];
            a2 += w2.x * zin[c] + w2.y * zin[c + 1] + w2.z * zin[c + 2] + w2.w * zin[c + 3];
            a3 += w3.x * zin[c] + w3.y * zin[c + 1] + w3.z * zin[c + 2] + w3.w * zin[c + 3];
        }
        *(float4*)(trow + og * 4) = make_float4(a0, a1, a2, a3);
        float h0 = tf32_rna(a0), h1 = tf32_rna(a1), h2 = tf32_rna(a2), h3 = tf32_rna(a3);
        *(float4*)(hrow + og * 4) = make_float4(h0, h1, h2, h3);
        *(float4*)(lrow + og * 4) = make_float4(a0 - h0, a1 - h1, a2 - h2, a3 - h3);
    }
}

// ---------------------------------------------------------------------------
// Tensor-core distance argmin (3xTF32).
// Block = 128 tokens (8 warps x 16). Loop 64 chunks of 64 codes.
// Warp tile: m16 tokens x n8 codes per mma; 8 n-tiles per chunk.
// A fragments (token hi/lo for all 8 k-steps) live in registers.
#define EPITCH 68   // float2 pitch: bank-pair index (4g+tg) mod 16 -> conflict-free
__global__ void __launch_bounds__(256) k_argmin_tc() {
    __shared__ float2 shE[64 * EPITCH];  // (hi,lo) interleaved, padded rows
    __shared__ float  shEh[64];

    int tid  = threadIdx.x;
    int w    = tid >> 5;
    int lane = tid & 31;
    int g    = lane >> 2;   // groupID
    int tg   = lane & 3;    // thread-in-group
    int tok0 = blockIdx.x * 128;
    int trow0 = tok0 + w * 16;

    // Load A fragments: rows g / g+8, cols k*8+tg / k*8+tg+4, all 8 k-steps
    const float* Thi = g_thi + trow0 * NC;
    const float* Tlo = g_tlo + trow0 * NC;
    uint32_t ahi[8][4], alo[8][4];
#pragma unroll
    for (int k = 0; k < 8; k++) {
        int c0 = k * 8 + tg, c1 = k * 8 + tg + 4;
        ahi[k][0] = __float_as_uint(Thi[g * NC + c0]);
        ahi[k][1] = __float_as_uint(Thi[(g + 8) * NC + c0]);
        ahi[k][2] = __float_as_uint(Thi[g * NC + c1]);
        ahi[k][3] = __float_as_uint(Thi[(g + 8) * NC + c1]);
        alo[k][0] = __float_as_uint(Tlo[g * NC + c0]);
        alo[k][1] = __float_as_uint(Tlo[(g + 8) * NC + c0]);
        alo[k][2] = __float_as_uint(Tlo[g * NC + c1]);
        alo[k][3] = __float_as_uint(Tlo[(g + 8) * NC + c1]);
    }

    float bestD0 = 1e30f, bestD1 = 1e30f;
    int   bestI0 = 0,     bestI1 = 0;

    for (int kc = 0; kc < 64; kc++) {
        __syncthreads();
        // stage E chunk (64 codes x 64 c, hi/lo float2) + eh
        const float2* src = (const float2*)(g_ehl) + kc * 64 * NC;
        for (int i = tid; i < 64 * NC; i += 256) {
            int code = i >> 6, c = i & 63;
            shE[code * EPITCH + c] = src[code * NC + c];
        }
        if (tid < 64) shEh[tid] = g_eh[kc * 64 + tid];
        __syncthreads();

#pragma unroll 1
        for (int nt = 0; nt < 8; nt++) {
            float c0 = 0.f, c1 = 0.f, c2 = 0.f, c3 = 0.f;
            const float2* bp = shE + (nt * 8 + g) * EPITCH;  // B col(n) = groupID
#pragma unroll
            for (int k = 0; k < 8; k++) {
                float2 b0 = bp[k * 8 + tg];       // B row(k) = tg
                float2 b1 = bp[k * 8 + tg + 4];   // B row(k) = tg+4
                uint32_t bh0 = __float_as_uint(b0.x), bh1 = __float_as_uint(b1.x);
                uint32_t bl0 = __float_as_uint(b0.y), bl1 = __float_as_uint(b1.y);
                mma_tf32(c0, c1, c2, c3, ahi[k][0], ahi[k][1], ahi[k][2], ahi[k][3], bh0, bh1);
                mma_tf32(c0, c1, c2, c3, ahi[k][0], ahi[k][1], ahi[k][2], ahi[k][3], bl0, bl1);
                mma_tf32(c0, c1, c2, c3, alo[k][0], alo[k][1], alo[k][2], alo[k][3], bh0, bh1);
            }
            // C frag: c0:(row g, col 2tg) c1:(g,2tg+1) c2:(g+8,2tg) c3:(g+8,2tg+1)
            float2 eh2 = *(const float2*)&shEh[nt * 8 + 2 * tg];
            float d0 = eh2.x - c0;
            float d1 = eh2.y - c1;
            float d2 = eh2.x - c2;
            float d3 = eh2.y - c3;
            int base = kc * 64 + nt * 8 + 2 * tg;
            if (d0 < bestD0) { bestD0 = d0; bestI0 = base; }
            if (d1 < bestD0) { bestD0 = d1; bestI0 = base + 1; }
            if (d2 < bestD1) { bestD1 = d2; bestI1 = base; }
            if (d3 < bestD1) { bestD1 = d3; bestI1 = base + 1; }
        }
    }

    // reduce across the 4 tg lanes of each group (codes partitioned by col%8)
#pragma unroll
    for (int off = 1; off < 4; off <<= 1) {
        float vD0 = __shfl_xor_sync(0xffffffffu, bestD0, off);
        int   vI0 = __shfl_xor_sync(0xffffffffu, bestI0, off);
        float vD1 = __shfl_xor_sync(0xffffffffu, bestD1, off);
        int   vI1 = __shfl_xor_sync(0xffffffffu, bestI1, off);
        if (vD0 < bestD0 || (vD0 == bestD0 && vI0 < bestI0)) { bestD0 = vD0; bestI0 = vI0; }
        if (vD1 < bestD1 || (vD1 == bestD1 && vI1 < bestI1)) { bestD1 = vD1; bestI1 = vI1; }
    }
    if (tg == 0) {
        g_idx[trow0 + g]     = bestI0;
        g_idx[trow0 + g + 8] = bestI1;
    }
}

// ---------------------------------------------------------------------------
// gather codebook row, post-conv, loss accumulation, index output
__global__ void __launch_bounds__(256) k_post(const float* __restrict__ E,
                                              const float* __restrict__ w,
                                              const float* __restrict__ b,
                                              float* __restrict__ out) {
    __shared__ float shW[NC * NC];
    __shared__ float shB[NC];
    __shared__ float red[256];
    int tid = threadIdx.x;
    for (int i = tid; i < NC * NC; i += 256) shW[i] = w[i];
    if (tid < NC) shB[tid] = b[tid];
    __syncthreads();

    int n   = blockIdx.x * 256 + tid;
    int idx = g_idx[n];
    const float4* erow = (const float4*)(E + idx * NC);
    const float4* trow = (const float4*)(g_t + n * NC);

    float ein[NC];
    float loss = 0.0f;
#pragma unroll
    for (int i = 0; i < 16; i++) {
        float4 e4 = erow[i];
        float4 t4 = trow[i];
        ein[4 * i + 0] = e4.x; ein[4 * i + 1] = e4.y;
        ein[4 * i + 2] = e4.z; ein[4 * i + 3] = e4.w;
        float dx = e4.x - t4.x, dy = e4.y - t4.y;
        float dz = e4.z - t4.z, dw = e4.w - t4.w;
        loss += dx * dx + dy * dy + dz * dz + dw * dw;
    }

    int bb = n >> 15;
    int s  = n & 32767;
    float* op = out + bb * (NC * SPAT) + s;
#pragma unroll 1
    for (int og = 0; og < 16; og++) {
        float a0 = shB[og * 4 + 0], a1 = shB[og * 4 + 1];
        float a2 = shB[og * 4 + 2], a3 = shB[og * 4 + 3];
#pragma unroll
        for (int c = 0; c < NC; c += 4) {
            float4 w0 = *(const float4*)&shW[(og * 4 + 0) * NC + c];
            float4 w1 = *(const float4*)&shW[(og * 4 + 1) * NC + c];
            float4 w2 = *(const float4*)&shW[(og * 4 + 2) * NC + c];
            float4 w3 = *(const float4*)&shW[(og * 4 + 3) * NC + c];
            a0 += w0.x * ein[c] + w0.y * ein[c + 1] + w0.z * ein[c + 2] + w0.w * ein[c + 3];
            a1 += w1.x * ein[c] + w1.y * ein[c + 1] + w1.z * ein[c + 2] + w1.w * ein[c + 3];
            a2 += w2.x * ein[c] + w2.y * ein[c + 1] + w2.z * ein[c + 2] + w2.w * ein[c + 3];
            a3 += w3.x * ein[c] + w3.y * ein[c + 1] + w3.z * ein[c + 2] + w3.w * ein[c + 3];
        }
        op[(og * 4 + 0) * SPAT] = a0;
        op[(og * 4 + 1) * SPAT] = a1;
        op[(og * 4 + 2) * SPAT] = a2;
        op[(og * 4 + 3) * SPAT] = a3;
    }

    out[IDX_OFF + n] = (float)idx;

    red[tid] = loss;
    __syncthreads();
    for (int off = 128; off > 0; off >>= 1) {
        if (tid < off) red[tid] += red[tid + off];
        __syncthreads();
    }
    if (tid == 0) atomicAdd(&g_loss, red[0]);
}

__global__ void k_fin(float* __restrict__ out) {
    float v = g_loss * (1.0f / ((float)NTOK * (float)NC));
    out[LOSS_OFF]     = v;  // codebook_loss
    out[LOSS_OFF + 1] = v;  // commitment_loss (same forward value)
}

// ---------------------------------------------------------------------------
extern "C" void kernel_launch(void* const* d_in, const int* in_sizes, int n_in,
                              void* d_out, int out_size) {
    const float* z      = (const float*)d_in[0];
    const float* emb    = (const float*)d_in[1];
    const float* pre_w  = (const float*)d_in[2];
    const float* pre_b  = (const float*)d_in[3];
    const float* post_w = (const float*)d_in[4];
    const float* post_b = (const float*)d_in[5];
    float* out = (float*)d_out;

    k_eh<<<KCB / 256, 256>>>(emb);
    k_preconv<<<NTOK / 256, 256>>>(z, pre_w, pre_b);
    k_argmin_tc<<<NTOK / 128, 256>>>();
    k_post<<<NTOK / 256, 256>>>(emb, post_w, post_b, out);
    k_fin<<<1, 1>>>(out);
}